// round 1
// baseline (speedup 1.0000x reference)
#include <cuda_runtime.h>

typedef unsigned long long u64;

#define NITER 31
#define RPT 4
#define BLOCK 256
#define MAXBLOCKS 16384

__device__ double g_partials[MAXBLOCKS];

__device__ __forceinline__ u64 pk2(float a, float b) {
    u64 r; asm("mov.b64 %0, {%1, %2};" : "=l"(r) : "f"(a), "f"(b)); return r;
}
__device__ __forceinline__ void up2(u64 v, float &a, float &b) {
    asm("mov.b64 {%0, %1}, %2;" : "=f"(a), "=f"(b) : "l"(v));
}
__device__ __forceinline__ u64 ffma2(u64 a, u64 b, u64 c) {
    u64 d; asm("fma.rn.f32x2 %0, %1, %2, %3;" : "=l"(d) : "l"(a), "l"(b), "l"(c)); return d;
}
__device__ __forceinline__ u64 fmul2(u64 a, u64 b) {
    u64 d; asm("mul.rn.f32x2 %0, %1, %2;" : "=l"(d) : "l"(a), "l"(b)); return d;
}
__device__ __forceinline__ float frcp_(float x) {
    float r; asm("rcp.approx.f32 %0, %1;" : "=f"(r) : "f"(x)); return r;
}

// One LM iteration on a packed pair of rays.
__device__ __forceinline__ void lm_step(u64 A, u64 B, u64 C, u64 &t) {
    const u64 HALF2 = 0x3F0000003F000000ULL;  // (0.5f, 0.5f)
    const u64 NEG1  = 0xBF800000BF800000ULL;  // (-1.f, -1.f)
    u64 u   = ffma2(A, t, B);        // A*t + B
    u64 fp  = ffma2(A, t, u);        // 2A*t + B
    u64 f   = ffma2(u, t, C);        // A*t^2 + B*t + C
    u64 num = fmul2(f, fp);
    u64 den = ffma2(fp, fp, HALF2);  // fp^2 + damping
    float d0, d1; up2(den, d0, d1);
    u64 rr  = pk2(frcp_(d0), frcp_(d1));
    u64 dl  = fmul2(num, rr);        // delta
    float q0, q1; up2(dl, q0, q1);
    q0 = fminf(fmaxf(q0, -1000.0f), 1000.0f);
    q1 = fminf(fmaxf(q1, -1000.0f), 1000.0f);
    t = ffma2(pk2(q0, q1), NEG1, t); // t - clamp(delta)
}

__global__ void __launch_bounds__(BLOCK)
lm_kernel(const float* __restrict__ P, const float* __restrict__ V,
          const float* __restrict__ R, const float* __restrict__ T,
          const float* __restrict__ Cs, int n)
{
    const int g = blockIdx.x * BLOCK + threadIdx.x;
    const int base = g * RPT;

    float ssum = 0.0f;

    if (base < n) {
        const float r00 = __ldg(R + 0), r01 = __ldg(R + 1), r02 = __ldg(R + 2);
        const float r10 = __ldg(R + 3), r11 = __ldg(R + 4), r12 = __ldg(R + 5);
        const float r20 = __ldg(R + 6), r21 = __ldg(R + 7), r22 = __ldg(R + 8);
        const float tx = __ldg(T + 0), ty = __ldg(T + 1), tz = __ldg(T + 2);
        const float c   = __ldg(Cs);
        const float mc  = -c;
        const float m2c = -2.0f * c;

        float px[RPT], py[RPT], pz[RPT], wx[RPT], wy[RPT], wz[RPT];
        if (base + RPT <= n) {
            // 12 consecutive floats per array per thread -> 3 aligned float4 loads
            const float4* P4 = (const float4*)P;
            const float4* V4 = (const float4*)V;
            float4 a0 = P4[3*g + 0], a1 = P4[3*g + 1], a2 = P4[3*g + 2];
            float4 b0 = V4[3*g + 0], b1 = V4[3*g + 1], b2 = V4[3*g + 2];
            px[0]=a0.x; py[0]=a0.y; pz[0]=a0.z;
            px[1]=a0.w; py[1]=a1.x; pz[1]=a1.y;
            px[2]=a1.z; py[2]=a1.w; pz[2]=a2.x;
            px[3]=a2.y; py[3]=a2.z; pz[3]=a2.w;
            wx[0]=b0.x; wy[0]=b0.y; wz[0]=b0.z;
            wx[1]=b0.w; wy[1]=b1.x; wz[1]=b1.y;
            wx[2]=b1.z; wy[2]=b1.w; wz[2]=b2.x;
            wx[3]=b2.y; wy[3]=b2.z; wz[3]=b2.w;
        } else {
            #pragma unroll
            for (int k = 0; k < RPT; ++k) {
                int i = base + k;
                if (i < n) {
                    px[k]=P[3*i]; py[k]=P[3*i+1]; pz[k]=P[3*i+2];
                    wx[k]=V[3*i]; wy[k]=V[3*i+1]; wz[k]=V[3*i+2];
                } else {
                    px[k]=py[k]=pz[k]=wx[k]=wy[k]=wz[k]=0.0f;
                }
            }
        }

        // Transform to local frame and reduce each ray to quadratic (A,B,C)
        float Ak[RPT], Bk[RPT], Ck[RPT];
        #pragma unroll
        for (int k = 0; k < RPT; ++k) {
            float qx = px[k] - tx, qy = py[k] - ty, qz = pz[k] - tz;
            float plx = qx*r00 + qy*r10 + qz*r20;
            float ply = qx*r01 + qy*r11 + qz*r21;
            float plz = qx*r02 + qy*r12 + qz*r22;
            float vlx = wx[k]*r00 + wy[k]*r10 + wz[k]*r20;
            float vly = wx[k]*r01 + wy[k]*r11 + wz[k]*r21;
            float vlz = wx[k]*r02 + wy[k]*r12 + wz[k]*r22;
            Ak[k] = mc * (vly*vly + vlz*vlz);
            Bk[k] = fmaf(m2c, ply*vly + plz*vlz, vlx);
            Ck[k] = fmaf(mc,  ply*ply + plz*plz, plx);
        }

        const u64 A0 = pk2(Ak[0], Ak[1]), B0 = pk2(Bk[0], Bk[1]), C0 = pk2(Ck[0], Ck[1]);
        const u64 A1 = pk2(Ak[2], Ak[3]), B1 = pk2(Bk[2], Bk[3]), C1 = pk2(Ck[2], Ck[3]);
        u64 t0 = 0ULL, t1 = 0ULL;   // bits of (0.f, 0.f)

        #pragma unroll
        for (int it = 0; it < NITER; ++it) {
            lm_step(A0, B0, C0, t0);  // two independent chains for ILP
            lm_step(A1, B1, C1, t1);
        }

        // Final residual F = f(t_final) (scale == 1.0), accumulate F^2
        u64 u0 = ffma2(A0, t0, B0); u64 f0 = ffma2(u0, t0, C0);
        u64 u1 = ffma2(A1, t1, B1); u64 f1 = ffma2(u1, t1, C1);
        u64 ss = fmul2(f0, f0);
        ss = ffma2(f1, f1, ss);
        float sa, sb; up2(ss, sa, sb);
        ssum = sa + sb;
    }

    // Block tree reduction (float), per-block partial in double
    #pragma unroll
    for (int o = 16; o > 0; o >>= 1)
        ssum += __shfl_xor_sync(0xffffffffu, ssum, o);
    __shared__ float wsum[BLOCK / 32];
    if ((threadIdx.x & 31) == 0) wsum[threadIdx.x >> 5] = ssum;
    __syncthreads();
    if (threadIdx.x < 32) {
        float v = (threadIdx.x < BLOCK / 32) ? wsum[threadIdx.x] : 0.0f;
        #pragma unroll
        for (int o = 16; o > 0; o >>= 1)
            v += __shfl_xor_sync(0xffffffffu, v, o);
        if (threadIdx.x == 0) g_partials[blockIdx.x] = (double)v;
    }
}

__global__ void __launch_bounds__(1024)
reduce_kernel(const float* __restrict__ loss_in, float* __restrict__ out,
              int nblocks, double invN)
{
    double s = 0.0;
    for (int i = threadIdx.x; i < nblocks; i += blockDim.x)
        s += g_partials[i];
    #pragma unroll
    for (int o = 16; o > 0; o >>= 1)
        s += __shfl_xor_sync(0xffffffffu, s, o);
    __shared__ double ws[32];
    if ((threadIdx.x & 31) == 0) ws[threadIdx.x >> 5] = s;
    __syncthreads();
    if (threadIdx.x < 32) {
        double v = ws[threadIdx.x];   // blockDim=1024 -> exactly 32 warps
        #pragma unroll
        for (int o = 16; o > 0; o >>= 1)
            v += __shfl_xor_sync(0xffffffffu, v, o);
        if (threadIdx.x == 0)
            out[0] = (float)((double)loss_in[0] + v * invN);
    }
}

extern "C" void kernel_launch(void* const* d_in, const int* in_sizes, int n_in,
                              void* d_out, int out_size)
{
    const float* P       = (const float*)d_in[0];
    const float* V       = (const float*)d_in[1];
    const float* R       = (const float*)d_in[2];
    const float* T       = (const float*)d_in[3];
    const float* c       = (const float*)d_in[4];
    const float* loss_in = (const float*)d_in[5];

    const int n = in_sizes[0] / 3;                       // number of rays
    int nthreads = (n + RPT - 1) / RPT;
    int nblocks  = (nthreads + BLOCK - 1) / BLOCK;
    if (nblocks > MAXBLOCKS) nblocks = MAXBLOCKS;        // shape-fixed: 4096 for N=4.19M

    lm_kernel<<<nblocks, BLOCK>>>(P, V, R, T, c, n);
    reduce_kernel<<<1, 1024>>>(loss_in, (float*)d_out, nblocks, 1.0 / (double)n);
}

// round 2
// speedup vs baseline: 1.0927x; 1.0927x over previous
#include <cuda_runtime.h>

typedef unsigned long long u64;

#define NITER 31
#define RPT 4
#define BLOCK 256

__device__ double   g_sum   = 0.0;
__device__ unsigned g_count = 0;

__device__ __forceinline__ u64 pk2(float a, float b) {
    u64 r; asm("mov.b64 %0, {%1, %2};" : "=l"(r) : "f"(a), "f"(b)); return r;
}
__device__ __forceinline__ void up2(u64 v, float &a, float &b) {
    asm("mov.b64 {%0, %1}, %2;" : "=f"(a), "=f"(b) : "l"(v));
}
__device__ __forceinline__ u64 ffma2(u64 a, u64 b, u64 c) {
    u64 d; asm("fma.rn.f32x2 %0, %1, %2, %3;" : "=l"(d) : "l"(a), "l"(b), "l"(c)); return d;
}
__device__ __forceinline__ u64 fmul2(u64 a, u64 b) {
    u64 d; asm("mul.rn.f32x2 %0, %1, %2;" : "=l"(d) : "l"(a), "l"(b)); return d;
}
__device__ __forceinline__ float frcp_(float x) {
    float r; asm("rcp.approx.f32 %0, %1;" : "=f"(r) : "f"(x)); return r;
}
// clamp(x, +/-K) in ONE instruction: sign(x)^sign(K)=sign(x), mag=min(|x|,K)
__device__ __forceinline__ float clamp1k(float x) {
    float r; asm("min.xorsign.abs.f32 %0, %1, %2;" : "=f"(r) : "f"(x), "f"(1000.0f));
    return r;
}

// One LM iteration on a packed pair of rays.
__device__ __forceinline__ void lm_step(u64 A, u64 B, u64 C, u64 &t) {
    const u64 HALF2 = 0x3F0000003F000000ULL;  // (0.5f, 0.5f)
    const u64 NEG1  = 0xBF800000BF800000ULL;  // (-1.f, -1.f)
    u64 u   = ffma2(A, t, B);        // A*t + B
    u64 fp  = ffma2(A, t, u);        // 2A*t + B
    u64 f   = ffma2(u, t, C);        // A*t^2 + B*t + C
    u64 num = fmul2(f, fp);
    u64 den = ffma2(fp, fp, HALF2);  // fp^2 + damping
    float d0, d1; up2(den, d0, d1);
    u64 rr  = pk2(frcp_(d0), frcp_(d1));
    u64 dl  = fmul2(num, rr);        // delta
    float q0, q1; up2(dl, q0, q1);
    q0 = clamp1k(q0);
    q1 = clamp1k(q1);
    t = ffma2(pk2(q0, q1), NEG1, t); // t - clamp(delta)
}

__global__ void __launch_bounds__(BLOCK)
lm_kernel(const float* __restrict__ P, const float* __restrict__ V,
          const float* __restrict__ R, const float* __restrict__ T,
          const float* __restrict__ Cs, const float* __restrict__ loss_in,
          float* __restrict__ out, int n, double invN)
{
    const int g = blockIdx.x * BLOCK + threadIdx.x;
    const int base = g * RPT;

    float ssum = 0.0f;

    if (base < n) {
        const float r00 = __ldg(R + 0), r01 = __ldg(R + 1), r02 = __ldg(R + 2);
        const float r10 = __ldg(R + 3), r11 = __ldg(R + 4), r12 = __ldg(R + 5);
        const float r20 = __ldg(R + 6), r21 = __ldg(R + 7), r22 = __ldg(R + 8);
        const float tx = __ldg(T + 0), ty = __ldg(T + 1), tz = __ldg(T + 2);
        const float c   = __ldg(Cs);
        const float mc  = -c;
        const float m2c = -2.0f * c;

        float px[RPT], py[RPT], pz[RPT], wx[RPT], wy[RPT], wz[RPT];
        if (base + RPT <= n) {
            const float4* P4 = (const float4*)P;
            const float4* V4 = (const float4*)V;
            float4 a0 = P4[3*g + 0], a1 = P4[3*g + 1], a2 = P4[3*g + 2];
            float4 b0 = V4[3*g + 0], b1 = V4[3*g + 1], b2 = V4[3*g + 2];
            px[0]=a0.x; py[0]=a0.y; pz[0]=a0.z;
            px[1]=a0.w; py[1]=a1.x; pz[1]=a1.y;
            px[2]=a1.z; py[2]=a1.w; pz[2]=a2.x;
            px[3]=a2.y; py[3]=a2.z; pz[3]=a2.w;
            wx[0]=b0.x; wy[0]=b0.y; wz[0]=b0.z;
            wx[1]=b0.w; wy[1]=b1.x; wz[1]=b1.y;
            wx[2]=b1.z; wy[2]=b1.w; wz[2]=b2.x;
            wx[3]=b2.y; wy[3]=b2.z; wz[3]=b2.w;
        } else {
            #pragma unroll
            for (int k = 0; k < RPT; ++k) {
                int i = base + k;
                if (i < n) {
                    px[k]=P[3*i]; py[k]=P[3*i+1]; pz[k]=P[3*i+2];
                    wx[k]=V[3*i]; wy[k]=V[3*i+1]; wz[k]=V[3*i+2];
                } else {
                    px[k]=py[k]=pz[k]=wx[k]=wy[k]=wz[k]=0.0f;
                }
            }
        }

        // Transform to local frame; each ray reduces to quadratic f(t)=A t^2+B t+C
        float Ak[RPT], Bk[RPT], Ck[RPT];
        #pragma unroll
        for (int k = 0; k < RPT; ++k) {
            float qx = px[k] - tx, qy = py[k] - ty, qz = pz[k] - tz;
            float plx = qx*r00 + qy*r10 + qz*r20;
            float ply = qx*r01 + qy*r11 + qz*r21;
            float plz = qx*r02 + qy*r12 + qz*r22;
            float vlx = wx[k]*r00 + wy[k]*r10 + wz[k]*r20;
            float vly = wx[k]*r01 + wy[k]*r11 + wz[k]*r21;
            float vlz = wx[k]*r02 + wy[k]*r12 + wz[k]*r22;
            Ak[k] = mc * (vly*vly + vlz*vlz);
            Bk[k] = fmaf(m2c, ply*vly + plz*vlz, vlx);
            Ck[k] = fmaf(mc,  ply*ply + plz*plz, plx);
        }

        const u64 A0 = pk2(Ak[0], Ak[1]), B0 = pk2(Bk[0], Bk[1]), C0 = pk2(Ck[0], Ck[1]);
        const u64 A1 = pk2(Ak[2], Ak[3]), B1 = pk2(Bk[2], Bk[3]), C1 = pk2(Ck[2], Ck[3]);
        u64 t0 = 0ULL, t1 = 0ULL;

        #pragma unroll
        for (int it = 0; it < NITER; ++it) {
            lm_step(A0, B0, C0, t0);   // two independent chains for ILP
            lm_step(A1, B1, C1, t1);
        }

        // Final residual F = f(t_final) (scale == 1.0), accumulate F^2
        u64 u0 = ffma2(A0, t0, B0); u64 f0 = ffma2(u0, t0, C0);
        u64 u1 = ffma2(A1, t1, B1); u64 f1 = ffma2(u1, t1, C1);
        u64 ss = fmul2(f0, f0);
        ss = ffma2(f1, f1, ss);
        float sa, sb; up2(ss, sa, sb);
        ssum = sa + sb;
    }

    // Block tree reduction (float)
    #pragma unroll
    for (int o = 16; o > 0; o >>= 1)
        ssum += __shfl_xor_sync(0xffffffffu, ssum, o);
    __shared__ float wsum[BLOCK / 32];
    if ((threadIdx.x & 31) == 0) wsum[threadIdx.x >> 5] = ssum;
    __syncthreads();

    // Thread 0: global double accumulation + last-block finalize (self-resetting
    // so the kernel is graph-replayable with identical behavior each replay).
    if (threadIdx.x == 0) {
        float bsum = 0.0f;
        #pragma unroll
        for (int w = 0; w < BLOCK / 32; ++w) bsum += wsum[w];
        atomicAdd(&g_sum, (double)bsum);
        __threadfence();
        unsigned old = atomicAdd(&g_count, 1u);
        if (old == gridDim.x - 1) {
            __threadfence();
            double tot = g_sum;
            out[0] = (float)((double)loss_in[0] + tot * invN);
            g_sum = 0.0;          // reset for next graph replay
            __threadfence();
            g_count = 0;
        }
    }
}

extern "C" void kernel_launch(void* const* d_in, const int* in_sizes, int n_in,
                              void* d_out, int out_size)
{
    const float* P       = (const float*)d_in[0];
    const float* V       = (const float*)d_in[1];
    const float* R       = (const float*)d_in[2];
    const float* T       = (const float*)d_in[3];
    const float* c       = (const float*)d_in[4];
    const float* loss_in = (const float*)d_in[5];

    const int n = in_sizes[0] / 3;                 // number of rays
    int nthreads = (n + RPT - 1) / RPT;
    int nblocks  = (nthreads + BLOCK - 1) / BLOCK; // 4096 for N=4.19M

    lm_kernel<<<nblocks, BLOCK>>>(P, V, R, T, c, loss_in,
                                  (float*)d_out, n, 1.0 / (double)n);
}

// round 3
// speedup vs baseline: 1.4130x; 1.2932x over previous
#include <cuda_runtime.h>

typedef unsigned long long u64;

#define NITER 31
#define RPT 4
#define BLOCK 256

__device__ double   g_sum   = 0.0;
__device__ unsigned g_count = 0;

__device__ __forceinline__ u64 pk2(float a, float b) {
    u64 r; asm("mov.b64 %0, {%1, %2};" : "=l"(r) : "f"(a), "f"(b)); return r;
}
__device__ __forceinline__ void up2(u64 v, float &a, float &b) {
    asm("mov.b64 {%0, %1}, %2;" : "=f"(a), "=f"(b) : "l"(v));
}
__device__ __forceinline__ u64 ffma2(u64 a, u64 b, u64 c) {
    u64 d; asm("fma.rn.f32x2 %0, %1, %2, %3;" : "=l"(d) : "l"(a), "l"(b), "l"(c)); return d;
}
__device__ __forceinline__ u64 fmul2(u64 a, u64 b) {
    u64 d; asm("mul.rn.f32x2 %0, %1, %2;" : "=l"(d) : "l"(a), "l"(b)); return d;
}
__device__ __forceinline__ float frcp_(float x) {
    float r; asm("rcp.approx.f32 %0, %1;" : "=f"(r) : "f"(x)); return r;
}

__global__ void __launch_bounds__(BLOCK)
lm_kernel(const float* __restrict__ P, const float* __restrict__ V,
          const float* __restrict__ R, const float* __restrict__ T,
          const float* __restrict__ Cs, const float* __restrict__ loss_in,
          float* __restrict__ out, int n, double invN)
{
    const int g = blockIdx.x * BLOCK + threadIdx.x;
    const int base = g * RPT;

    float ssum = 0.0f;

    if (base < n) {
        const float r00 = __ldg(R + 0), r01 = __ldg(R + 1), r02 = __ldg(R + 2);
        const float r10 = __ldg(R + 3), r11 = __ldg(R + 4), r12 = __ldg(R + 5);
        const float r20 = __ldg(R + 6), r21 = __ldg(R + 7), r22 = __ldg(R + 8);
        const float tx = __ldg(T + 0), ty = __ldg(T + 1), tz = __ldg(T + 2);
        const float c   = __ldg(Cs);
        const float mc  = -c;
        const float m2c = -2.0f * c;

        float px[RPT], py[RPT], pz[RPT], wx[RPT], wy[RPT], wz[RPT];
        if (base + RPT <= n) {
            const float4* P4 = (const float4*)P;
            const float4* V4 = (const float4*)V;
            float4 a0 = P4[3*g + 0], a1 = P4[3*g + 1], a2 = P4[3*g + 2];
            float4 b0 = V4[3*g + 0], b1 = V4[3*g + 1], b2 = V4[3*g + 2];
            px[0]=a0.x; py[0]=a0.y; pz[0]=a0.z;
            px[1]=a0.w; py[1]=a1.x; pz[1]=a1.y;
            px[2]=a1.z; py[2]=a1.w; pz[2]=a2.x;
            px[3]=a2.y; py[3]=a2.z; pz[3]=a2.w;
            wx[0]=b0.x; wy[0]=b0.y; wz[0]=b0.z;
            wx[1]=b0.w; wy[1]=b1.x; wz[1]=b1.y;
            wx[2]=b1.z; wy[2]=b1.w; wz[2]=b2.x;
            wx[3]=b2.y; wy[3]=b2.z; wz[3]=b2.w;
        } else {
            #pragma unroll
            for (int k = 0; k < RPT; ++k) {
                int i = base + k;
                if (i < n) {
                    px[k]=P[3*i]; py[k]=P[3*i+1]; pz[k]=P[3*i+2];
                    wx[k]=V[3*i]; wy[k]=V[3*i+1]; wz[k]=V[3*i+2];
                } else {
                    // dummy ray: A=1,B=1,C=0 -> D=1, s=1 is an exact fixed
                    // point and F = (s^2-D)/(4A) = 0
                    px[k]=0.f; py[k]=0.f; pz[k]=0.f;
                    wx[k]=1.f; wy[k]=0.f; wz[k]=0.f;
                }
            }
        }

        // Per ray: transform to local frame, reduce f(t)=A t^2 + B t + C,
        // then substitute s = 2At + B:  s' = s - s(s^2-D)/(2 s^2 + 1),
        // D = B^2 - 4AC, final F = (s^2 - D)/(4A).
        float Dk[RPT], Sk[RPT], I4[RPT];
        #pragma unroll
        for (int k = 0; k < RPT; ++k) {
            float qx = px[k] - tx, qy = py[k] - ty, qz = pz[k] - tz;
            float plx = qx*r00 + qy*r10 + qz*r20;
            float ply = qx*r01 + qy*r11 + qz*r21;
            float plz = qx*r02 + qy*r12 + qz*r22;
            float vlx = wx[k]*r00 + wy[k]*r10 + wz[k]*r20;
            float vly = wx[k]*r01 + wy[k]*r11 + wz[k]*r21;
            float vlz = wx[k]*r02 + wy[k]*r12 + wz[k]*r22;
            float A = mc * (vly*vly + vlz*vlz);
            float B = fmaf(m2c, ply*vly + plz*vlz, vlx);
            float C = fmaf(mc,  ply*ply + plz*plz, plx);
            // degenerate dummy path (wy=wz=0 gives A=0): remap to safe A=1,B=1,C=0
            if (A == 0.0f) { A = 1.0f; B = 1.0f; C = 0.0f; }
            float AC = A * C;
            Dk[k] = fmaf(AC, -4.0f, B * B);   // D = B^2 - 4AC
            Sk[k] = B;                        // s0 = 2A*0 + B
            I4[k] = frcp_(4.0f * A);          // 1/(4A) for the epilogue
        }

        const u64 NEG1 = 0xBF800000BF800000ULL;  // (-1, -1)
        const u64 TWO2 = 0x4000000040000000ULL;  // ( 2,  2)
        const u64 ONE2 = 0x3F8000003F800000ULL;  // ( 1,  1)

        const u64 D0 = pk2(Dk[0], Dk[1]), D1 = pk2(Dk[2], Dk[3]);
        u64 s0 = pk2(Sk[0], Sk[1]),       s1 = pk2(Sk[2], Sk[3]);

        #pragma unroll
        for (int it = 0; it < NITER; ++it) {
            u64 q0 = fmul2(s0, s0);
            u64 q1 = fmul2(s1, s1);
            u64 w0 = ffma2(q0, NEG1, D0);    // D - s^2  (negated numerator)
            u64 w1 = ffma2(q1, NEG1, D1);
            u64 d0 = ffma2(q0, TWO2, ONE2);  // 2 s^2 + 1  (>= 1 always)
            u64 d1 = ffma2(q1, TWO2, ONE2);
            u64 n0 = fmul2(s0, w0);          // -s (s^2 - D)
            u64 n1 = fmul2(s1, w1);
            u64 m  = fmul2(d0, d1);          // lane-wise product of both dens
            float ma, mb; up2(m, ma, mb);
            u64 rp = pk2(frcp_(ma), frcp_(mb));
            u64 r0 = fmul2(rp, d1);          // 1/d0 per lane
            u64 r1 = fmul2(rp, d0);          // 1/d1 per lane
            s0 = ffma2(n0, r0, s0);          // s + (-s(s^2-D))/(2s^2+1)
            s1 = ffma2(n1, r1, s1);
        }

        // F = (s^2 - D) / (4A); accumulate F^2 (sign-free)
        const u64 I40 = pk2(I4[0], I4[1]), I41 = pk2(I4[2], I4[3]);
        u64 q0 = fmul2(s0, s0);
        u64 q1 = fmul2(s1, s1);
        u64 w0 = ffma2(q0, NEG1, D0);        // D - s^2 = -num
        u64 w1 = ffma2(q1, NEG1, D1);
        u64 F0 = fmul2(w0, I40);             // -F
        u64 F1 = fmul2(w1, I41);
        u64 ss = fmul2(F0, F0);
        ss = ffma2(F1, F1, ss);
        float sa, sb; up2(ss, sa, sb);
        ssum = sa + sb;
    }

    // Block tree reduction (float)
    #pragma unroll
    for (int o = 16; o > 0; o >>= 1)
        ssum += __shfl_xor_sync(0xffffffffu, ssum, o);
    __shared__ float wsum[BLOCK / 32];
    if ((threadIdx.x & 31) == 0) wsum[threadIdx.x >> 5] = ssum;
    __syncthreads();

    // Global double accumulation + last-block finalize (self-resetting for
    // identical behavior on every graph replay).
    if (threadIdx.x == 0) {
        float bsum = 0.0f;
        #pragma unroll
        for (int w = 0; w < BLOCK / 32; ++w) bsum += wsum[w];
        atomicAdd(&g_sum, (double)bsum);
        __threadfence();
        unsigned old = atomicAdd(&g_count, 1u);
        if (old == gridDim.x - 1) {
            __threadfence();
            double tot = g_sum;
            out[0] = (float)((double)loss_in[0] + tot * invN);
            g_sum = 0.0;
            __threadfence();
            g_count = 0;
        }
    }
}

extern "C" void kernel_launch(void* const* d_in, const int* in_sizes, int n_in,
                              void* d_out, int out_size)
{
    const float* P       = (const float*)d_in[0];
    const float* V       = (const float*)d_in[1];
    const float* R       = (const float*)d_in[2];
    const float* T       = (const float*)d_in[3];
    const float* c       = (const float*)d_in[4];
    const float* loss_in = (const float*)d_in[5];

    const int n = in_sizes[0] / 3;                 // number of rays
    int nthreads = (n + RPT - 1) / RPT;
    int nblocks  = (nthreads + BLOCK - 1) / BLOCK; // 4096 for N=4.19M

    lm_kernel<<<nblocks, BLOCK>>>(P, V, R, T, c, loss_in,
                                  (float*)d_out, n, 1.0 / (double)n);
}